// round 10
// baseline (speedup 1.0000x reference)
#include <cuda_runtime.h>

#define CUTOFF 8.0f
#define MAXK 32
#define MAXE (1 << 20)

// Per-edge precompute: (ux*SC, uy*SC, uz*SC, f(|r|)) where u = r/|r| and
// SC = sqrt((K-1)/2) so that dot of two table vectors = inv_hg * cos.
__device__ float4 g_edge[MAXE];
// Fallback-path coefficient storage (generic K only).
__device__ float4 g_fc[MAXK];
__device__ float4 g_gc[MAXK];
__device__ int    g_deg;

// ===========================================================================
// Compile-time-K natural cubic spline (uniform knots). All-register Thomas.
// ===========================================================================
template <int K>
__device__ __forceinline__ void build_spline_reg(const float* __restrict__ y,
                                                 float h, float4* sh_out) {
    float yv[K];
#pragma unroll
    for (int i = 0; i < K; i++) yv[i] = y[i];

    const float inv_h = 1.0f / h;
    float dy[K - 1];
#pragma unroll
    for (int i = 0; i < K - 1; i++) dy[i] = (yv[i + 1] - yv[i]) * inv_h;

    constexpr int n = K - 2;
    float M[K];
    M[0] = 0.0f;
    M[K - 1] = 0.0f;
    if (n > 0) {
        float cp[n], dp[n];
        cp[0] = 0.25f;
        dp[0] = 6.0f * (dy[1] - dy[0]) * inv_h * 0.25f;
#pragma unroll
        for (int i = 1; i < n; i++) {
            float rd = 1.0f / (4.0f - cp[i - 1]);
            cp[i] = rd;
            dp[i] = (6.0f * (dy[i + 1] - dy[i]) * inv_h - dp[i - 1]) * rd;
        }
        M[n] = dp[n - 1];
#pragma unroll
        for (int i = n - 2; i >= 0; i--) M[i + 1] = dp[i] - cp[i] * M[i + 2];
    }

    constexpr float SIXTH = 1.0f / 6.0f;
#pragma unroll
    for (int i = 0; i < K - 1; i++) {
        sh_out[i] = make_float4(yv[i],
                                dy[i] - h * (2.0f * M[i] + M[i + 1]) * SIXTH,
                                0.5f * M[i],
                                (M[i + 1] - M[i]) * inv_h * SIXTH);
    }
}

// ===========================================================================
// Kernel 1: per-edge precompute. r staged through shared (coalesced loads,
// stride-3 conflict-free readback). Writes SCALED unit vector + f(|r|).
// ===========================================================================
template <int K>
__global__ void __launch_bounds__(256) smeam_edge_kernel(
    const float* __restrict__ r, const float* __restrict__ fy, int E) {
    __shared__ float4 sf[K - 1];
    __shared__ float s_r[256 * 3];
    if (threadIdx.x == 0) build_spline_reg<K>(fy, CUTOFF / (float)(K - 1), sf);

    const int base = blockIdx.x * 256 * 3;
#pragma unroll
    for (int k = 0; k < 3; k++) {
        int off = k * 256 + threadIdx.x;
        int gidx = base + off;
        if (gidx < 3 * E) s_r[off] = r[gidx];
    }
    __syncthreads();

    int i = blockIdx.x * blockDim.x + threadIdx.x;
    if (i >= E) return;

    float x = s_r[3 * threadIdx.x + 0];
    float y = s_r[3 * threadIdx.x + 1];
    float z = s_r[3 * threadIdx.x + 2];
    float d2 = x * x + y * y + z * z;
    float invl = rsqrtf(d2);
    float l = d2 * invl;

    constexpr float hf = CUTOFF / (float)(K - 1);
    constexpr float inv_hf = (float)(K - 1) / CUTOFF;
    int idx = min(max((int)(l * inv_hf), 0), K - 2);
    float s = fmaf((float)idx, -hf, l);
    float4 cf = sf[idx];
    float fv = fmaf(s, fmaf(s, fmaf(s, cf.w, cf.z), cf.y), cf.x);

    const float SC = sqrtf((float)(K - 1) * 0.5f);  // sqrt(inv_hg)
    float sl = invl * SC;
    g_edge[i] = make_float4(x * sl, y * sl, z * sl, fv);
}

// ===========================================================================
// g-spline eval on scaled vectors + unit-interval coefficients.
// t = inv_hg*(1 - cos) comes straight out of the FFMA dot chain.
// ===========================================================================
template <int K>
__device__ __forceinline__ float eval_g(float4 P, float4 u2, int s1, int d2,
                                        const float4* __restrict__ sg,
                                        float acc) {
    constexpr float inv_hg = (float)(K - 1) * 0.5f;
    float t = fmaf(-P.x, u2.x, fmaf(-P.y, u2.y, fmaf(-P.z, u2.z, inv_hg)));
    int idx = min((int)t, K - 2);        // trunc: tiny-negative t -> 0
    float s = t - (float)idx;
    float4 cf = sg[idx];
    float gv = fmaf(s, fmaf(s, fmaf(s, cf.w, cf.z), cf.y), cf.x);
    if (s1 != d2) acc = fmaf(P.w, gv, acc);
    return acc;
}

// ===========================================================================
// Group worker: full groups of 4 e2 (2 per 16-lane half) + scalar tail.
// One-stage software pipeline on the src-pair load (breaks the 2-hop
// address chain: src[eA] -> partner gather). FULL=true specializes deg==32.
// ===========================================================================
template <int K, bool FULL>
__device__ __forceinline__ void do_groups(
    const int* __restrict__ src, const int* __restrict__ dst,
    float* __restrict__ out, const float4* __restrict__ sg,
    int E, int deg, int shift, int warp, int TW, int hl, int grp) {
    const int jh = FULL ? hl : ((hl < deg) ? hl : 0);
    const int jH = FULL ? (hl + 16) : ((hl + 16 < deg) ? (hl + 16) : 0);
    const bool m0 = FULL || (hl < deg);
    const bool m1 = FULL || (hl + 16 < deg);
    const int ng = E >> 2;   // full groups

    // prefetch first group's src pair
    int2 s2n = make_int2(0, 0);
    if (warp < ng)
        s2n = *reinterpret_cast<const int2*>(src + warp * 4 + grp * 2);

    for (int g = warp; g < ng; g += TW) {
        const int eA = g * 4 + grp * 2;
        const int2 s2 = s2n;
        const int gn = g + TW;
        if (gn < ng)  // prefetch next group's src pair (overlaps this body)
            s2n = *reinterpret_cast<const int2*>(src + gn * 4 + grp * 2);

        const int baseA = s2.x * deg;
        const int baseB = s2.y * deg;

        float4 u2A = g_edge[eA];
        float4 u2B = g_edge[eA + 1];

        float4 PA0 = g_edge[baseA + jh];
        float4 PA1 = g_edge[baseA + jH];
        float4 PB0 = g_edge[baseB + jh];
        float4 PB1 = g_edge[baseB + jH];
        int sA0 = __ldg(src + baseA + jh);
        int sA1 = __ldg(src + baseA + jH);
        int sB0 = __ldg(src + baseB + jh);
        int sB1 = __ldg(src + baseB + jH);

        if (!FULL) {
            if (!m0) { PA0.w = 0.0f; PB0.w = 0.0f; }
            if (!m1) { PA1.w = 0.0f; PB1.w = 0.0f; }
        }

        int d2A, d2B;
        if (shift >= 0) {
            d2A = eA >> shift;
            d2B = (eA + 1) >> shift;
        } else {
            int2 dd = *reinterpret_cast<const int2*>(dst + eA);
            d2A = dd.x; d2B = dd.y;
        }

        float accA = 0.0f, accB = 0.0f;
        accA = eval_g<K>(PA0, u2A, sA0, d2A, sg, accA);
        accA = eval_g<K>(PA1, u2A, sA1, d2A, sg, accA);
        accB = eval_g<K>(PB0, u2B, sB0, d2B, sg, accB);
        accB = eval_g<K>(PB1, u2B, sB1, d2B, sg, accB);

#pragma unroll
        for (int o = 8; o; o >>= 1) {
            accA += __shfl_xor_sync(0xffffffffu, accA, o);
            accB += __shfl_xor_sync(0xffffffffu, accB, o);
        }
        if (hl == 0) {
            *reinterpret_cast<float2*>(out + eA) =
                make_float2(accA * u2A.w, accB * u2B.w);
        }
    }

    // tail: remaining e2 in [E&~3, E), at most 3. Both halves compute the
    // same e2 redundantly; reduce within half; lane 0 of grp 0 stores.
    {
        int e2 = (E & ~3) + warp;
        if (e2 < E) {
            float4 u2 = g_edge[e2];
            int s2v = __ldg(src + e2);
            int base = s2v * deg;
            float4 P0 = g_edge[base + jh];
            float4 P1 = g_edge[base + jH];
            int s0 = __ldg(src + base + jh);
            int s1v = __ldg(src + base + jH);
            if (!m0) P0.w = 0.0f;
            if (!m1) P1.w = 0.0f;
            int d2 = (shift >= 0) ? (e2 >> shift) : __ldg(dst + e2);
            float acc = 0.0f;
            acc = eval_g<K>(P0, u2, s0, d2, sg, acc);
            acc = eval_g<K>(P1, u2, s1v, d2, sg, acc);
#pragma unroll
            for (int o = 8; o; o >>= 1)
                acc += __shfl_xor_sync(0xffffffffu, acc, o);
            if (hl == 0 && grp == 0) out[e2] = acc * u2.w;
        }
    }
}

// ===========================================================================
// Kernel 2 (main, persistent gather): 128-thread blocks, 10 resident/SM,
// single-wave grid, grid-stride over e2-groups.
// ===========================================================================
template <int K>
__global__ void __launch_bounds__(128, 10) smeam_main_gather(
    const int* __restrict__ src, const int* __restrict__ dst,
    const float* __restrict__ gy, float* __restrict__ out, int E) {
    __shared__ float4 sg[K - 1];
    __shared__ int sh_deg, sh_shift;
    if (threadIdx.x == 0) {
        build_spline_reg<K>(gy, 2.0f / (float)(K - 1), sg);
        // rescale to unit-interval parameter: value = a + s(b*h + s(c*h^2 + s d*h^3))
        constexpr float hg = 2.0f / (float)(K - 1);
#pragma unroll
        for (int i = 0; i < K - 1; i++) {
            float4 c = sg[i];
            sg[i] = make_float4(c.x, c.y * hg, c.z * hg * hg, c.w * hg * hg * hg);
        }
        int N = __ldg(&dst[E - 1]) + 1;
        int deg = E / N;
        sh_deg = deg;
        sh_shift = ((deg & (deg - 1)) == 0) ? (__ffs(deg) - 1) : -1;
    }
    __syncthreads();

    const int deg = sh_deg;
    const int shift = sh_shift;
    const int lane = threadIdx.x & 31;
    const int hl = lane & 15;
    const int grp = lane >> 4;
    const int warp = (blockIdx.x * blockDim.x + threadIdx.x) >> 5;
    const int TW = (gridDim.x * blockDim.x) >> 5;

    if (deg == 32) {
        do_groups<K, true>(src, dst, out, sg, E, deg, shift, warp, TW, hl, grp);
    } else if (deg <= 32) {
        do_groups<K, false>(src, dst, out, sg, E, deg, shift, warp, TW, hl, grp);
    } else {
        // deg > 32: one warp per e2, grid-stride, strip-mined partner loop.
        for (int e2 = warp; e2 < E; e2 += TW) {
            float4 u2 = g_edge[e2];
            int s2 = __ldg(&src[e2]);
            int d2v = (shift >= 0) ? (e2 >> shift) : __ldg(&dst[e2]);
            float acc = 0.0f;
            for (int j = lane; j < deg; j += 32) {
                float4 P = g_edge[s2 * deg + j];
                int s1 = __ldg(&src[s2 * deg + j]);
                acc = eval_g<K>(P, u2, s1, d2v, sg, acc);
            }
#pragma unroll
            for (int o = 16; o; o >>= 1)
                acc += __shfl_xor_sync(0xffffffffu, acc, o);
            if (lane == 0) out[e2] = acc * u2.w;
        }
    }
}

// ===========================================================================
// Generic-K fallback (runtime K) — correctness-only path (unscaled table).
// ===========================================================================
__device__ void build_spline_rt(const float* y, int K, float h, float4* outc) {
    double dy[MAXK];
    for (int i = 0; i < K - 1; i++) dy[i] = ((double)y[i + 1] - (double)y[i]) / (double)h;
    int n = K - 2;
    double M[MAXK];
    for (int i = 0; i < K; i++) M[i] = 0.0;
    if (n > 0) {
        double cp[MAXK], dp[MAXK];
        double hh = (double)h;
        cp[0] = hh / (4.0 * hh);
        dp[0] = 6.0 * (dy[1] - dy[0]) / (4.0 * hh);
        for (int i = 1; i < n; i++) {
            double denom = 4.0 * hh - hh * cp[i - 1];
            cp[i] = hh / denom;
            dp[i] = (6.0 * (dy[i + 1] - dy[i]) - hh * dp[i - 1]) / denom;
        }
        double x = dp[n - 1];
        M[n] = x;
        for (int i = n - 2; i >= 0; i--) { x = dp[i] - cp[i] * x; M[i + 1] = x; }
    }
    for (int i = 0; i < K - 1; i++) {
        outc[i] = make_float4((float)y[i],
                              (float)(dy[i] - (double)h * (2.0 * M[i] + M[i + 1]) / 6.0),
                              (float)(M[i] / 2.0),
                              (float)((M[i + 1] - M[i]) / (6.0 * (double)h)));
    }
}

__global__ void smeam_build_kernel_rt(const float* fy, const float* gy,
                                      const int* dst, int E, int K) {
    int N = dst[E - 1] + 1;
    g_deg = E / N;
    build_spline_rt(fy, K, CUTOFF / (float)(K - 1), g_fc);
    build_spline_rt(gy, K, 2.0f / (float)(K - 1), g_gc);
}

__global__ void smeam_edge_kernel_rt(const float* __restrict__ r, int E, int K) {
    int i = blockIdx.x * blockDim.x + threadIdx.x;
    if (i >= E) return;
    float x = r[3 * i + 0], y = r[3 * i + 1], z = r[3 * i + 2];
    float d2 = x * x + y * y + z * z;
    float invl = rsqrtf(d2);
    float l = d2 * invl;
    float hf = CUTOFF / (float)(K - 1);
    float inv_hf = (float)(K - 1) / CUTOFF;
    int idx = min(max((int)floorf(l * inv_hf), 0), K - 2);
    float s = l - (float)idx * hf;
    float4 cf = g_fc[idx];
    g_edge[i] = make_float4(x * invl, y * invl, z * invl,
                            cf.x + s * (cf.y + s * (cf.z + s * cf.w)));
}

__global__ void smeam_main_kernel_rt(const int* __restrict__ src,
                                     const int* __restrict__ dst,
                                     float* __restrict__ out, int E, int K) {
    int warp = (blockIdx.x * blockDim.x + threadIdx.x) >> 5;
    int lane = threadIdx.x & 31;
    if (warp >= E) return;
    int e2 = warp;
    float4 u2 = g_edge[e2];
    int s2 = src[e2], d2 = dst[e2];
    int deg = g_deg;
    float hg = 2.0f / (float)(K - 1);
    float inv_hg = (float)(K - 1) * 0.5f;
    float acc = 0.0f;
    for (int j = lane; j < deg; j += 32) {
        int e1 = s2 * deg + j;
        float4 u1 = g_edge[e1];
        int s1 = src[e1];
        float c = -(u1.x * u2.x + u1.y * u2.y + u1.z * u2.z);
        c = fminf(fmaxf(c, -1.0f), 1.0f);
        float xc = c + 1.0f;
        int idx = min(max((int)floorf(xc * inv_hg), 0), K - 2);
        float s = xc - (float)idx * hg;
        float4 cf = g_gc[idx];
        float gv = cf.x + s * (cf.y + s * (cf.z + s * cf.w));
        acc += (s1 != d2) ? u1.w * u2.w * gv : 0.0f;
    }
#pragma unroll
    for (int o = 16; o; o >>= 1) acc += __shfl_down_sync(0xffffffffu, acc, o);
    if (lane == 0) out[e2] = acc;
}

// ===========================================================================
template <int K>
static void launch_ct(const float* r, const float* fy, const float* gy,
                      const int* src, const int* dst, float* out, int E) {
    smeam_edge_kernel<K><<<(E + 255) / 256, 256>>>(r, fy, E);
    // Single-wave persistent grid: 10 resident blocks/SM (forced by launch
    // bounds) x 148 SMs = 1480 blocks of 128 threads.
    const int t = 128;
    int need_warps = (E + 3) / 4;               // deg<=32 path demand
    int need_blocks = (need_warps * 32 + t - 1) / t;
    int blocks = 1480;
    if (need_blocks < blocks) blocks = need_blocks;
    if (blocks < 1) blocks = 1;
    smeam_main_gather<K><<<blocks, t>>>(src, dst, gy, out, E);
}

extern "C" void kernel_launch(void* const* d_in, const int* in_sizes, int n_in,
                              void* d_out, int out_size) {
    const float* r   = (const float*)d_in[0];
    const float* fy  = (const float*)d_in[1];
    const float* gy  = (const float*)d_in[2];
    const int*   src = (const int*)d_in[3];
    const int*   dst = (const int*)d_in[4];
    float*       out = (float*)d_out;

    int E = in_sizes[3];
    int K = in_sizes[1];

    switch (K) {
        case 3: launch_ct<3>(r, fy, gy, src, dst, out, E); break;
        case 4: launch_ct<4>(r, fy, gy, src, dst, out, E); break;
        case 5: launch_ct<5>(r, fy, gy, src, dst, out, E); break;
        case 6: launch_ct<6>(r, fy, gy, src, dst, out, E); break;
        case 7: launch_ct<7>(r, fy, gy, src, dst, out, E); break;
        case 8: launch_ct<8>(r, fy, gy, src, dst, out, E); break;
        case 9: launch_ct<9>(r, fy, gy, src, dst, out, E); break;
        default: {
            smeam_build_kernel_rt<<<1, 1>>>(fy, gy, dst, E, K);
            int t = 256;
            smeam_edge_kernel_rt<<<(E + t - 1) / t, t>>>(r, E, K);
            long total = (long)E * 32;
            unsigned blocks = (unsigned)((total + t - 1) / t);
            smeam_main_kernel_rt<<<blocks, t>>>(src, dst, out, E, K);
            break;
        }
    }
}

// round 11
// speedup vs baseline: 1.0817x; 1.0817x over previous
#include <cuda_runtime.h>

#define CUTOFF 8.0f
#define MAXK 32
#define MAXE (1 << 20)

// Per-edge precompute: (ux*SC, uy*SC, uz*SC, f(|r|)) where u = r/|r| and
// SC = sqrt((K-1)/2) so that dot of two table vectors = inv_hg * cos.
// When N < 16384, the 14-bit src id of the edge is embedded in the low
// mantissa bits of x (5), y (5), z (4)  — perturbation <= 2^-18.
__device__ float4 g_edge[MAXE];
__device__ int    g_packed;   // 1 if src ids are embedded in g_edge
// Fallback-path coefficient storage (generic K only).
__device__ float4 g_fc[MAXK];
__device__ float4 g_gc[MAXK];
__device__ int    g_deg;

__device__ __forceinline__ int unpack_src(float4 P) {
    unsigned bx = __float_as_uint(P.x);
    unsigned by = __float_as_uint(P.y);
    unsigned bz = __float_as_uint(P.z);
    return (int)(((bx & 31u) << 9) | ((by & 31u) << 4) | (bz & 15u));
}

// ===========================================================================
// Compile-time-K natural cubic spline (uniform knots). All-register Thomas.
// ===========================================================================
template <int K>
__device__ __forceinline__ void build_spline_reg(const float* __restrict__ y,
                                                 float h, float4* sh_out) {
    float yv[K];
#pragma unroll
    for (int i = 0; i < K; i++) yv[i] = y[i];

    const float inv_h = 1.0f / h;
    float dy[K - 1];
#pragma unroll
    for (int i = 0; i < K - 1; i++) dy[i] = (yv[i + 1] - yv[i]) * inv_h;

    constexpr int n = K - 2;
    float M[K];
    M[0] = 0.0f;
    M[K - 1] = 0.0f;
    if (n > 0) {
        float cp[n], dp[n];
        cp[0] = 0.25f;
        dp[0] = 6.0f * (dy[1] - dy[0]) * inv_h * 0.25f;
#pragma unroll
        for (int i = 1; i < n; i++) {
            float rd = 1.0f / (4.0f - cp[i - 1]);
            cp[i] = rd;
            dp[i] = (6.0f * (dy[i + 1] - dy[i]) * inv_h - dp[i - 1]) * rd;
        }
        M[n] = dp[n - 1];
#pragma unroll
        for (int i = n - 2; i >= 0; i--) M[i + 1] = dp[i] - cp[i] * M[i + 2];
    }

    constexpr float SIXTH = 1.0f / 6.0f;
#pragma unroll
    for (int i = 0; i < K - 1; i++) {
        sh_out[i] = make_float4(yv[i],
                                dy[i] - h * (2.0f * M[i] + M[i + 1]) * SIXTH,
                                0.5f * M[i],
                                (M[i + 1] - M[i]) * inv_h * SIXTH);
    }
}

// ===========================================================================
// Kernel 1: per-edge precompute. r staged through shared; writes SCALED unit
// vector + f(|r|), with src id packed into mantissa bits when N < 16384.
// ===========================================================================
template <int K>
__global__ void __launch_bounds__(256) smeam_edge_kernel(
    const float* __restrict__ r, const float* __restrict__ fy,
    const int* __restrict__ src, const int* __restrict__ dst, int E) {
    __shared__ float4 sf[K - 1];
    __shared__ float s_r[256 * 3];
    __shared__ int sh_pack;
    if (threadIdx.x == 0) {
        build_spline_reg<K>(fy, CUTOFF / (float)(K - 1), sf);
        int N = __ldg(&dst[E - 1]) + 1;
        int pk = (N < 16384) ? 1 : 0;
        sh_pack = pk;
        g_packed = pk;   // benign duplicate writes across blocks
    }

    const int base = blockIdx.x * 256 * 3;
#pragma unroll
    for (int k = 0; k < 3; k++) {
        int off = k * 256 + threadIdx.x;
        int gidx = base + off;
        if (gidx < 3 * E) s_r[off] = r[gidx];
    }
    __syncthreads();

    int i = blockIdx.x * blockDim.x + threadIdx.x;
    if (i >= E) return;

    float x = s_r[3 * threadIdx.x + 0];
    float y = s_r[3 * threadIdx.x + 1];
    float z = s_r[3 * threadIdx.x + 2];
    float d2 = x * x + y * y + z * z;
    float invl = rsqrtf(d2);
    float l = d2 * invl;

    constexpr float hf = CUTOFF / (float)(K - 1);
    constexpr float inv_hf = (float)(K - 1) / CUTOFF;
    int idx = min(max((int)(l * inv_hf), 0), K - 2);
    float s = fmaf((float)idx, -hf, l);
    float4 cf = sf[idx];
    float fv = fmaf(s, fmaf(s, fmaf(s, cf.w, cf.z), cf.y), cf.x);

    const float SC = sqrtf((float)(K - 1) * 0.5f);  // sqrt(inv_hg)
    float sl = invl * SC;
    float px = x * sl, py = y * sl, pz = z * sl;

    if (sh_pack) {
        unsigned sv = (unsigned)__ldg(&src[i]);
        unsigned bx = (__float_as_uint(px) & ~31u) | ((sv >> 9) & 31u);
        unsigned by = (__float_as_uint(py) & ~31u) | ((sv >> 4) & 31u);
        unsigned bz = (__float_as_uint(pz) & ~15u) | (sv & 15u);
        px = __uint_as_float(bx);
        py = __uint_as_float(by);
        pz = __uint_as_float(bz);
    }
    g_edge[i] = make_float4(px, py, pz, fv);
}

// ===========================================================================
// g-spline eval on scaled vectors + unit-interval coefficients.
// t = inv_hg*(1 - cos) comes straight out of the FFMA dot chain.
// ===========================================================================
template <int K>
__device__ __forceinline__ float eval_g(float4 P, float4 u2, int s1, int d2,
                                        const float4* __restrict__ sg,
                                        float acc) {
    constexpr float inv_hg = (float)(K - 1) * 0.5f;
    float t = fmaf(-P.x, u2.x, fmaf(-P.y, u2.y, fmaf(-P.z, u2.z, inv_hg)));
    int idx = min((int)t, K - 2);        // trunc: tiny-negative t -> 0
    float s = t - (float)idx;
    float4 cf = sg[idx];
    float gv = fmaf(s, fmaf(s, fmaf(s, cf.w, cf.z), cf.y), cf.x);
    if (s1 != d2) acc = fmaf(P.w, gv, acc);
    return acc;
}

// ===========================================================================
// Group worker: full groups of 4 e2 (2 per 16-lane half) + scalar tail.
// FULL=true specializes deg==32. PACKED=true derives partner src from the
// mantissa bits of the partner record (no src gather stream).
// ===========================================================================
template <int K, bool FULL, bool PACKED>
__device__ __forceinline__ void do_groups(
    const int* __restrict__ src, const int* __restrict__ dst,
    float* __restrict__ out, const float4* __restrict__ sg,
    int E, int deg, int shift, int warp, int TW, int hl, int grp) {
    const int jh = FULL ? hl : ((hl < deg) ? hl : 0);
    const int jH = FULL ? (hl + 16) : ((hl + 16 < deg) ? (hl + 16) : 0);
    const bool m0 = FULL || (hl < deg);
    const bool m1 = FULL || (hl + 16 < deg);
    const int ng = E >> 2;   // full groups

    for (int g = warp; g < ng; g += TW) {
        const int eA = g * 4 + grp * 2;

        int2 s2 = *reinterpret_cast<const int2*>(src + eA);
        const int baseA = s2.x * deg;
        const int baseB = s2.y * deg;

        float4 u2A = g_edge[eA];
        float4 u2B = g_edge[eA + 1];

        float4 PA0 = g_edge[baseA + jh];
        float4 PA1 = g_edge[baseA + jH];
        float4 PB0 = g_edge[baseB + jh];
        float4 PB1 = g_edge[baseB + jH];
        int sA0, sA1, sB0, sB1;
        if (PACKED) {
            sA0 = unpack_src(PA0);
            sA1 = unpack_src(PA1);
            sB0 = unpack_src(PB0);
            sB1 = unpack_src(PB1);
        } else {
            sA0 = __ldg(src + baseA + jh);
            sA1 = __ldg(src + baseA + jH);
            sB0 = __ldg(src + baseB + jh);
            sB1 = __ldg(src + baseB + jH);
        }

        if (!FULL) {
            if (!m0) { PA0.w = 0.0f; PB0.w = 0.0f; }
            if (!m1) { PA1.w = 0.0f; PB1.w = 0.0f; }
        }

        int d2A, d2B;
        if (shift >= 0) {
            d2A = eA >> shift;
            d2B = (eA + 1) >> shift;
        } else {
            int2 dd = *reinterpret_cast<const int2*>(dst + eA);
            d2A = dd.x; d2B = dd.y;
        }

        float accA = 0.0f, accB = 0.0f;
        accA = eval_g<K>(PA0, u2A, sA0, d2A, sg, accA);
        accA = eval_g<K>(PA1, u2A, sA1, d2A, sg, accA);
        accB = eval_g<K>(PB0, u2B, sB0, d2B, sg, accB);
        accB = eval_g<K>(PB1, u2B, sB1, d2B, sg, accB);

#pragma unroll
        for (int o = 8; o; o >>= 1) {
            accA += __shfl_xor_sync(0xffffffffu, accA, o);
            accB += __shfl_xor_sync(0xffffffffu, accB, o);
        }
        if (hl == 0) {
            *reinterpret_cast<float2*>(out + eA) =
                make_float2(accA * u2A.w, accB * u2B.w);
        }
    }

    // tail: remaining e2 in [E&~3, E), at most 3.
    {
        int e2 = (E & ~3) + warp;
        if (e2 < E) {
            float4 u2 = g_edge[e2];
            int s2v = __ldg(src + e2);
            int base = s2v * deg;
            float4 P0 = g_edge[base + jh];
            float4 P1 = g_edge[base + jH];
            int s0, s1v;
            if (PACKED) {
                s0 = unpack_src(P0);
                s1v = unpack_src(P1);
            } else {
                s0 = __ldg(src + base + jh);
                s1v = __ldg(src + base + jH);
            }
            if (!m0) P0.w = 0.0f;
            if (!m1) P1.w = 0.0f;
            int d2 = (shift >= 0) ? (e2 >> shift) : __ldg(dst + e2);
            float acc = 0.0f;
            acc = eval_g<K>(P0, u2, s0, d2, sg, acc);
            acc = eval_g<K>(P1, u2, s1v, d2, sg, acc);
#pragma unroll
            for (int o = 8; o; o >>= 1)
                acc += __shfl_xor_sync(0xffffffffu, acc, o);
            if (hl == 0 && grp == 0) out[e2] = acc * u2.w;
        }
    }
}

// ===========================================================================
// Kernel 2 (main, persistent gather): 256-thread blocks, single-wave grid,
// grid-stride over e2-groups.
// ===========================================================================
template <int K>
__global__ void __launch_bounds__(256) smeam_main_gather(
    const int* __restrict__ src, const int* __restrict__ dst,
    const float* __restrict__ gy, float* __restrict__ out, int E) {
    __shared__ float4 sg[K - 1];
    __shared__ int sh_deg, sh_shift, sh_pack;
    if (threadIdx.x == 0) {
        build_spline_reg<K>(gy, 2.0f / (float)(K - 1), sg);
        // rescale to unit-interval parameter
        constexpr float hg = 2.0f / (float)(K - 1);
#pragma unroll
        for (int i = 0; i < K - 1; i++) {
            float4 c = sg[i];
            sg[i] = make_float4(c.x, c.y * hg, c.z * hg * hg, c.w * hg * hg * hg);
        }
        int N = __ldg(&dst[E - 1]) + 1;
        int deg = E / N;
        sh_deg = deg;
        sh_shift = ((deg & (deg - 1)) == 0) ? (__ffs(deg) - 1) : -1;
        sh_pack = g_packed;
    }
    __syncthreads();

    const int deg = sh_deg;
    const int shift = sh_shift;
    const int packed = sh_pack;
    const int lane = threadIdx.x & 31;
    const int hl = lane & 15;
    const int grp = lane >> 4;
    const int warp = (blockIdx.x * blockDim.x + threadIdx.x) >> 5;
    const int TW = (gridDim.x * blockDim.x) >> 5;

    if (deg == 32) {
        if (packed)
            do_groups<K, true, true>(src, dst, out, sg, E, deg, shift, warp, TW, hl, grp);
        else
            do_groups<K, true, false>(src, dst, out, sg, E, deg, shift, warp, TW, hl, grp);
    } else if (deg <= 32) {
        if (packed)
            do_groups<K, false, true>(src, dst, out, sg, E, deg, shift, warp, TW, hl, grp);
        else
            do_groups<K, false, false>(src, dst, out, sg, E, deg, shift, warp, TW, hl, grp);
    } else {
        // deg > 32: one warp per e2, grid-stride, strip-mined partner loop.
        for (int e2 = warp; e2 < E; e2 += TW) {
            float4 u2 = g_edge[e2];
            int s2 = __ldg(&src[e2]);
            int d2v = (shift >= 0) ? (e2 >> shift) : __ldg(&dst[e2]);
            float acc = 0.0f;
            for (int j = lane; j < deg; j += 32) {
                float4 P = g_edge[s2 * deg + j];
                int s1 = packed ? unpack_src(P) : __ldg(&src[s2 * deg + j]);
                acc = eval_g<K>(P, u2, s1, d2v, sg, acc);
            }
#pragma unroll
            for (int o = 16; o; o >>= 1)
                acc += __shfl_xor_sync(0xffffffffu, acc, o);
            if (lane == 0) out[e2] = acc * u2.w;
        }
    }
}

// ===========================================================================
// Generic-K fallback (runtime K) — correctness-only path (unscaled table).
// ===========================================================================
__device__ void build_spline_rt(const float* y, int K, float h, float4* outc) {
    double dy[MAXK];
    for (int i = 0; i < K - 1; i++) dy[i] = ((double)y[i + 1] - (double)y[i]) / (double)h;
    int n = K - 2;
    double M[MAXK];
    for (int i = 0; i < K; i++) M[i] = 0.0;
    if (n > 0) {
        double cp[MAXK], dp[MAXK];
        double hh = (double)h;
        cp[0] = hh / (4.0 * hh);
        dp[0] = 6.0 * (dy[1] - dy[0]) / (4.0 * hh);
        for (int i = 1; i < n; i++) {
            double denom = 4.0 * hh - hh * cp[i - 1];
            cp[i] = hh / denom;
            dp[i] = (6.0 * (dy[i + 1] - dy[i]) - hh * dp[i - 1]) / denom;
        }
        double x = dp[n - 1];
        M[n] = x;
        for (int i = n - 2; i >= 0; i--) { x = dp[i] - cp[i] * x; M[i + 1] = x; }
    }
    for (int i = 0; i < K - 1; i++) {
        outc[i] = make_float4((float)y[i],
                              (float)(dy[i] - (double)h * (2.0 * M[i] + M[i + 1]) / 6.0),
                              (float)(M[i] / 2.0),
                              (float)((M[i + 1] - M[i]) / (6.0 * (double)h)));
    }
}

__global__ void smeam_build_kernel_rt(const float* fy, const float* gy,
                                      const int* dst, int E, int K) {
    int N = dst[E - 1] + 1;
    g_deg = E / N;
    build_spline_rt(fy, K, CUTOFF / (float)(K - 1), g_fc);
    build_spline_rt(gy, K, 2.0f / (float)(K - 1), g_gc);
}

__global__ void smeam_edge_kernel_rt(const float* __restrict__ r, int E, int K) {
    int i = blockIdx.x * blockDim.x + threadIdx.x;
    if (i >= E) return;
    float x = r[3 * i + 0], y = r[3 * i + 1], z = r[3 * i + 2];
    float d2 = x * x + y * y + z * z;
    float invl = rsqrtf(d2);
    float l = d2 * invl;
    float hf = CUTOFF / (float)(K - 1);
    float inv_hf = (float)(K - 1) / CUTOFF;
    int idx = min(max((int)floorf(l * inv_hf), 0), K - 2);
    float s = l - (float)idx * hf;
    float4 cf = g_fc[idx];
    g_edge[i] = make_float4(x * invl, y * invl, z * invl,
                            cf.x + s * (cf.y + s * (cf.z + s * cf.w)));
}

__global__ void smeam_main_kernel_rt(const int* __restrict__ src,
                                     const int* __restrict__ dst,
                                     float* __restrict__ out, int E, int K) {
    int warp = (blockIdx.x * blockDim.x + threadIdx.x) >> 5;
    int lane = threadIdx.x & 31;
    if (warp >= E) return;
    int e2 = warp;
    float4 u2 = g_edge[e2];
    int s2 = src[e2], d2 = dst[e2];
    int deg = g_deg;
    float hg = 2.0f / (float)(K - 1);
    float inv_hg = (float)(K - 1) * 0.5f;
    float acc = 0.0f;
    for (int j = lane; j < deg; j += 32) {
        int e1 = s2 * deg + j;
        float4 u1 = g_edge[e1];
        int s1 = src[e1];
        float c = -(u1.x * u2.x + u1.y * u2.y + u1.z * u2.z);
        c = fminf(fmaxf(c, -1.0f), 1.0f);
        float xc = c + 1.0f;
        int idx = min(max((int)floorf(xc * inv_hg), 0), K - 2);
        float s = xc - (float)idx * hg;
        float4 cf = g_gc[idx];
        float gv = cf.x + s * (cf.y + s * (cf.z + s * cf.w));
        acc += (s1 != d2) ? u1.w * u2.w * gv : 0.0f;
    }
#pragma unroll
    for (int o = 16; o; o >>= 1) acc += __shfl_down_sync(0xffffffffu, acc, o);
    if (lane == 0) out[e2] = acc;
}

// ===========================================================================
template <int K>
static void launch_ct(const float* r, const float* fy, const float* gy,
                      const int* src, const int* dst, float* out, int E) {
    smeam_edge_kernel<K><<<(E + 255) / 256, 256>>>(r, fy, src, dst, E);
    // Single-wave persistent grid: ~5 resident blocks/SM at natural regs
    // x 148 SMs = 740 blocks of 256 threads.
    const int t = 256;
    int need_warps = (E + 3) / 4;               // deg<=32 path demand
    int need_blocks = (need_warps * 32 + t - 1) / t;
    int blocks = 740;
    if (need_blocks < blocks) blocks = need_blocks;
    if (blocks < 1) blocks = 1;
    smeam_main_gather<K><<<blocks, t>>>(src, dst, gy, out, E);
}

extern "C" void kernel_launch(void* const* d_in, const int* in_sizes, int n_in,
                              void* d_out, int out_size) {
    const float* r   = (const float*)d_in[0];
    const float* fy  = (const float*)d_in[1];
    const float* gy  = (const float*)d_in[2];
    const int*   src = (const int*)d_in[3];
    const int*   dst = (const int*)d_in[4];
    float*       out = (float*)d_out;

    int E = in_sizes[3];
    int K = in_sizes[1];

    switch (K) {
        case 3: launch_ct<3>(r, fy, gy, src, dst, out, E); break;
        case 4: launch_ct<4>(r, fy, gy, src, dst, out, E); break;
        case 5: launch_ct<5>(r, fy, gy, src, dst, out, E); break;
        case 6: launch_ct<6>(r, fy, gy, src, dst, out, E); break;
        case 7: launch_ct<7>(r, fy, gy, src, dst, out, E); break;
        case 8: launch_ct<8>(r, fy, gy, src, dst, out, E); break;
        case 9: launch_ct<9>(r, fy, gy, src, dst, out, E); break;
        default: {
            smeam_build_kernel_rt<<<1, 1>>>(fy, gy, dst, E, K);
            int t = 256;
            smeam_edge_kernel_rt<<<(E + t - 1) / t, t>>>(r, E, K);
            long total = (long)E * 32;
            unsigned blocks = (unsigned)((total + t - 1) / t);
            smeam_main_kernel_rt<<<blocks, t>>>(src, dst, out, E, K);
            break;
        }
    }
}

// round 12
// speedup vs baseline: 1.2258x; 1.1331x over previous
#include <cuda_runtime.h>

#define CUTOFF 8.0f
#define MAXK 32
#define MAXE (1 << 20)

// Per-edge precompute: (ux*SC, uy*SC, uz*SC, f(|r|)) where u = r/|r| and
// SC = sqrt((K-1)/2) so that dot of two table vectors = inv_hg * cos.
// When N < 16384, the 14-bit src id of the edge is embedded in the low
// mantissa bits of x (5), y (5), z (4)  — perturbation <= 2^-18.
__device__ float4 g_edge[MAXE];
__device__ int    g_packed;   // 1 if src ids are embedded in g_edge
// Fallback-path coefficient storage (generic K only).
__device__ float4 g_fc[MAXK];
__device__ float4 g_gc[MAXK];
__device__ int    g_deg;

__device__ __forceinline__ int unpack_src(float4 P) {
    unsigned bx = __float_as_uint(P.x);
    unsigned by = __float_as_uint(P.y);
    unsigned bz = __float_as_uint(P.z);
    return (int)(((bx & 31u) << 9) | ((by & 31u) << 4) | (bz & 15u));
}

// ===========================================================================
// Compile-time-K natural cubic spline (uniform knots). All-register Thomas.
// ===========================================================================
template <int K>
__device__ __forceinline__ void build_spline_reg(const float* __restrict__ y,
                                                 float h, float4* sh_out) {
    float yv[K];
#pragma unroll
    for (int i = 0; i < K; i++) yv[i] = y[i];

    const float inv_h = 1.0f / h;
    float dy[K - 1];
#pragma unroll
    for (int i = 0; i < K - 1; i++) dy[i] = (yv[i + 1] - yv[i]) * inv_h;

    constexpr int n = K - 2;
    float M[K];
    M[0] = 0.0f;
    M[K - 1] = 0.0f;
    if (n > 0) {
        float cp[n], dp[n];
        cp[0] = 0.25f;
        dp[0] = 6.0f * (dy[1] - dy[0]) * inv_h * 0.25f;
#pragma unroll
        for (int i = 1; i < n; i++) {
            float rd = 1.0f / (4.0f - cp[i - 1]);
            cp[i] = rd;
            dp[i] = (6.0f * (dy[i + 1] - dy[i]) * inv_h - dp[i - 1]) * rd;
        }
        M[n] = dp[n - 1];
#pragma unroll
        for (int i = n - 2; i >= 0; i--) M[i + 1] = dp[i] - cp[i] * M[i + 2];
    }

    constexpr float SIXTH = 1.0f / 6.0f;
#pragma unroll
    for (int i = 0; i < K - 1; i++) {
        sh_out[i] = make_float4(yv[i],
                                dy[i] - h * (2.0f * M[i] + M[i + 1]) * SIXTH,
                                0.5f * M[i],
                                (M[i + 1] - M[i]) * inv_h * SIXTH);
    }
}

// ===========================================================================
// Kernel 1: per-edge precompute. r staged through shared; writes SCALED unit
// vector + f(|r|), with src id packed into mantissa bits when N < 16384.
// ===========================================================================
template <int K>
__global__ void __launch_bounds__(256) smeam_edge_kernel(
    const float* __restrict__ r, const float* __restrict__ fy,
    const int* __restrict__ src, const int* __restrict__ dst, int E) {
    __shared__ float4 sf[K - 1];
    __shared__ float s_r[256 * 3];
    __shared__ int sh_pack;
    if (threadIdx.x == 0) {
        build_spline_reg<K>(fy, CUTOFF / (float)(K - 1), sf);
        int N = __ldg(&dst[E - 1]) + 1;
        int pk = (N < 16384) ? 1 : 0;
        sh_pack = pk;
        g_packed = pk;   // benign duplicate writes across blocks
    }

    const int base = blockIdx.x * 256 * 3;
#pragma unroll
    for (int k = 0; k < 3; k++) {
        int off = k * 256 + threadIdx.x;
        int gidx = base + off;
        if (gidx < 3 * E) s_r[off] = r[gidx];
    }
    __syncthreads();

    int i = blockIdx.x * blockDim.x + threadIdx.x;
    if (i >= E) return;

    float x = s_r[3 * threadIdx.x + 0];
    float y = s_r[3 * threadIdx.x + 1];
    float z = s_r[3 * threadIdx.x + 2];
    float d2 = x * x + y * y + z * z;
    float invl = rsqrtf(d2);
    float l = d2 * invl;

    constexpr float hf = CUTOFF / (float)(K - 1);
    constexpr float inv_hf = (float)(K - 1) / CUTOFF;
    int idx = min(max((int)(l * inv_hf), 0), K - 2);
    float s = fmaf((float)idx, -hf, l);
    float4 cf = sf[idx];
    float fv = fmaf(s, fmaf(s, fmaf(s, cf.w, cf.z), cf.y), cf.x);

    const float SC = sqrtf((float)(K - 1) * 0.5f);  // sqrt(inv_hg)
    float sl = invl * SC;
    float px = x * sl, py = y * sl, pz = z * sl;

    if (sh_pack) {
        unsigned sv = (unsigned)__ldg(&src[i]);
        unsigned bx = (__float_as_uint(px) & ~31u) | ((sv >> 9) & 31u);
        unsigned by = (__float_as_uint(py) & ~31u) | ((sv >> 4) & 31u);
        unsigned bz = (__float_as_uint(pz) & ~15u) | (sv & 15u);
        px = __uint_as_float(bx);
        py = __uint_as_float(by);
        pz = __uint_as_float(bz);
    }
    g_edge[i] = make_float4(px, py, pz, fv);
}

// ===========================================================================
// g-spline eval on scaled vectors + unit-interval coefficients.
// t = inv_hg*(1 - cos) comes straight out of the FFMA dot chain.
// ===========================================================================
template <int K>
__device__ __forceinline__ float eval_g(float4 P, float4 u2, int s1, int d2,
                                        const float4* __restrict__ sg,
                                        float acc) {
    constexpr float inv_hg = (float)(K - 1) * 0.5f;
    float t = fmaf(-P.x, u2.x, fmaf(-P.y, u2.y, fmaf(-P.z, u2.z, inv_hg)));
    int idx = min((int)t, K - 2);        // trunc: tiny-negative t -> 0
    float s = t - (float)idx;
    float4 cf = sg[idx];
    float gv = fmaf(s, fmaf(s, fmaf(s, cf.w, cf.z), cf.y), cf.x);
    if (s1 != d2) acc = fmaf(P.w, gv, acc);
    return acc;
}

// ===========================================================================
// Quarter-split group worker (deg <= 32): quarter q = lane>>3 owns one e2;
// lane ql = lane&7 holds partners ql+{0,8,16,24}. Each warp iteration
// processes 8 e2 (two per quarter) with all loads batched up front.
// Reduction = 3-step butterfly within 8 lanes (all 4 quarters in parallel).
// FULL=true specializes deg==32. PACKED=true derives partner src from the
// mantissa bits of the partner record (no src gather stream).
// ===========================================================================
template <int K, bool FULL, bool PACKED>
__device__ __forceinline__ void do_groups(
    const int* __restrict__ src, const int* __restrict__ dst,
    float* __restrict__ out, const float4* __restrict__ sg,
    int E, int deg, int shift, int warp, int TW, int lane) {
    const int q = lane >> 3;
    const int ql = lane & 7;

    int j[4];
    bool m[4];
#pragma unroll
    for (int k = 0; k < 4; k++) {
        int jj = ql + 8 * k;
        m[k] = FULL || (jj < deg);
        j[k] = m[k] ? jj : 0;
    }

    const int ng = E >> 3;   // full groups of 8

    for (int g = warp; g < ng; g += TW) {
        const int eb = g * 8;
        const int e2a = eb + q;
        const int e2b = eb + 4 + q;

        // ---- batch all independent loads ----
        const int sa = __ldg(src + e2a);      // 4 consecutive ints (1 line)
        const int sb = __ldg(src + e2b);
        const int basea = sa * deg;
        const int baseb = sb * deg;

        float4 u2a = g_edge[e2a];             // 4 consecutive float4 (1 line)
        float4 u2b = g_edge[e2b];

        float4 PA[4], PB[4];
#pragma unroll
        for (int k = 0; k < 4; k++) PA[k] = g_edge[basea + j[k]];
#pragma unroll
        for (int k = 0; k < 4; k++) PB[k] = g_edge[baseb + j[k]];

        int sA[4], sB[4];
        if (PACKED) {
#pragma unroll
            for (int k = 0; k < 4; k++) { sA[k] = unpack_src(PA[k]); sB[k] = unpack_src(PB[k]); }
        } else {
#pragma unroll
            for (int k = 0; k < 4; k++) { sA[k] = __ldg(src + basea + j[k]); sB[k] = __ldg(src + baseb + j[k]); }
        }

        if (!FULL) {
#pragma unroll
            for (int k = 0; k < 4; k++) {
                if (!m[k]) { PA[k].w = 0.0f; PB[k].w = 0.0f; }
            }
        }

        int d2a, d2b;
        if (shift >= 0) {
            d2a = e2a >> shift;
            d2b = e2b >> shift;
        } else {
            d2a = __ldg(dst + e2a);
            d2b = __ldg(dst + e2b);
        }

        float acca = 0.0f, accb = 0.0f;
#pragma unroll
        for (int k = 0; k < 4; k++) {
            acca = eval_g<K>(PA[k], u2a, sA[k], d2a, sg, acca);
            accb = eval_g<K>(PB[k], u2b, sB[k], d2b, sg, accb);
        }

        // 3-step butterfly within each 8-lane quarter (both accs interleaved)
#pragma unroll
        for (int o = 4; o; o >>= 1) {
            acca += __shfl_xor_sync(0xffffffffu, acca, o);
            accb += __shfl_xor_sync(0xffffffffu, accb, o);
        }
        if (ql == 0) {
            out[e2a] = acca * u2a.w;          // 4 lanes -> 4 consecutive floats
            out[e2b] = accb * u2b.w;
        }
    }

    // tail: e2 in [E&~7, E), at most 7. One warp per e2, full-warp strip.
    {
        int e2 = (E & ~7) + warp;
        if (e2 < E) {
            float4 u2 = g_edge[e2];
            int s2v = __ldg(src + e2);
            int base = s2v * deg;
            int jj = (lane < deg) ? lane : 0;
            float4 P = g_edge[base + jj];
            int s1v = PACKED ? unpack_src(P) : __ldg(src + base + jj);
            if (lane >= deg) P.w = 0.0f;
            int d2 = (shift >= 0) ? (e2 >> shift) : __ldg(dst + e2);
            float acc = eval_g<K>(P, u2, s1v, d2, sg, 0.0f);
#pragma unroll
            for (int o = 16; o; o >>= 1)
                acc += __shfl_xor_sync(0xffffffffu, acc, o);
            if (lane == 0) out[e2] = acc * u2.w;
        }
    }
}

// ===========================================================================
// Kernel 2 (main, persistent gather): 256-thread blocks, single-wave grid,
// grid-stride over 8-e2 groups.
// ===========================================================================
template <int K>
__global__ void __launch_bounds__(256) smeam_main_gather(
    const int* __restrict__ src, const int* __restrict__ dst,
    const float* __restrict__ gy, float* __restrict__ out, int E) {
    __shared__ float4 sg[K - 1];
    __shared__ int sh_deg, sh_shift, sh_pack;
    if (threadIdx.x == 0) {
        build_spline_reg<K>(gy, 2.0f / (float)(K - 1), sg);
        // rescale to unit-interval parameter
        constexpr float hg = 2.0f / (float)(K - 1);
#pragma unroll
        for (int i = 0; i < K - 1; i++) {
            float4 c = sg[i];
            sg[i] = make_float4(c.x, c.y * hg, c.z * hg * hg, c.w * hg * hg * hg);
        }
        int N = __ldg(&dst[E - 1]) + 1;
        int deg = E / N;
        sh_deg = deg;
        sh_shift = ((deg & (deg - 1)) == 0) ? (__ffs(deg) - 1) : -1;
        sh_pack = g_packed;
    }
    __syncthreads();

    const int deg = sh_deg;
    const int shift = sh_shift;
    const int packed = sh_pack;
    const int lane = threadIdx.x & 31;
    const int warp = (blockIdx.x * blockDim.x + threadIdx.x) >> 5;
    const int TW = (gridDim.x * blockDim.x) >> 5;

    if (deg == 32) {
        if (packed)
            do_groups<K, true, true>(src, dst, out, sg, E, deg, shift, warp, TW, lane);
        else
            do_groups<K, true, false>(src, dst, out, sg, E, deg, shift, warp, TW, lane);
    } else if (deg <= 32) {
        if (packed)
            do_groups<K, false, true>(src, dst, out, sg, E, deg, shift, warp, TW, lane);
        else
            do_groups<K, false, false>(src, dst, out, sg, E, deg, shift, warp, TW, lane);
    } else {
        // deg > 32: one warp per e2, grid-stride, strip-mined partner loop.
        for (int e2 = warp; e2 < E; e2 += TW) {
            float4 u2 = g_edge[e2];
            int s2 = __ldg(&src[e2]);
            int d2v = (shift >= 0) ? (e2 >> shift) : __ldg(&dst[e2]);
            float acc = 0.0f;
            for (int jj = lane; jj < deg; jj += 32) {
                float4 P = g_edge[s2 * deg + jj];
                int s1 = packed ? unpack_src(P) : __ldg(&src[s2 * deg + jj]);
                acc = eval_g<K>(P, u2, s1, d2v, sg, acc);
            }
#pragma unroll
            for (int o = 16; o; o >>= 1)
                acc += __shfl_xor_sync(0xffffffffu, acc, o);
            if (lane == 0) out[e2] = acc * u2.w;
        }
    }
}

// ===========================================================================
// Generic-K fallback (runtime K) — correctness-only path (unscaled table).
// ===========================================================================
__device__ void build_spline_rt(const float* y, int K, float h, float4* outc) {
    double dy[MAXK];
    for (int i = 0; i < K - 1; i++) dy[i] = ((double)y[i + 1] - (double)y[i]) / (double)h;
    int n = K - 2;
    double M[MAXK];
    for (int i = 0; i < K; i++) M[i] = 0.0;
    if (n > 0) {
        double cp[MAXK], dp[MAXK];
        double hh = (double)h;
        cp[0] = hh / (4.0 * hh);
        dp[0] = 6.0 * (dy[1] - dy[0]) / (4.0 * hh);
        for (int i = 1; i < n; i++) {
            double denom = 4.0 * hh - hh * cp[i - 1];
            cp[i] = hh / denom;
            dp[i] = (6.0 * (dy[i + 1] - dy[i]) - hh * dp[i - 1]) / denom;
        }
        double x = dp[n - 1];
        M[n] = x;
        for (int i = n - 2; i >= 0; i--) { x = dp[i] - cp[i] * x; M[i + 1] = x; }
    }
    for (int i = 0; i < K - 1; i++) {
        outc[i] = make_float4((float)y[i],
                              (float)(dy[i] - (double)h * (2.0 * M[i] + M[i + 1]) / 6.0),
                              (float)(M[i] / 2.0),
                              (float)((M[i + 1] - M[i]) / (6.0 * (double)h)));
    }
}

__global__ void smeam_build_kernel_rt(const float* fy, const float* gy,
                                      const int* dst, int E, int K) {
    int N = dst[E - 1] + 1;
    g_deg = E / N;
    build_spline_rt(fy, K, CUTOFF / (float)(K - 1), g_fc);
    build_spline_rt(gy, K, 2.0f / (float)(K - 1), g_gc);
}

__global__ void smeam_edge_kernel_rt(const float* __restrict__ r, int E, int K) {
    int i = blockIdx.x * blockDim.x + threadIdx.x;
    if (i >= E) return;
    float x = r[3 * i + 0], y = r[3 * i + 1], z = r[3 * i + 2];
    float d2 = x * x + y * y + z * z;
    float invl = rsqrtf(d2);
    float l = d2 * invl;
    float hf = CUTOFF / (float)(K - 1);
    float inv_hf = (float)(K - 1) / CUTOFF;
    int idx = min(max((int)floorf(l * inv_hf), 0), K - 2);
    float s = l - (float)idx * hf;
    float4 cf = g_fc[idx];
    g_edge[i] = make_float4(x * invl, y * invl, z * invl,
                            cf.x + s * (cf.y + s * (cf.z + s * cf.w)));
}

__global__ void smeam_main_kernel_rt(const int* __restrict__ src,
                                     const int* __restrict__ dst,
                                     float* __restrict__ out, int E, int K) {
    int warp = (blockIdx.x * blockDim.x + threadIdx.x) >> 5;
    int lane = threadIdx.x & 31;
    if (warp >= E) return;
    int e2 = warp;
    float4 u2 = g_edge[e2];
    int s2 = src[e2], d2 = dst[e2];
    int deg = g_deg;
    float hg = 2.0f / (float)(K - 1);
    float inv_hg = (float)(K - 1) * 0.5f;
    float acc = 0.0f;
    for (int jj = lane; jj < deg; jj += 32) {
        int e1 = s2 * deg + jj;
        float4 u1 = g_edge[e1];
        int s1 = src[e1];
        float c = -(u1.x * u2.x + u1.y * u2.y + u1.z * u2.z);
        c = fminf(fmaxf(c, -1.0f), 1.0f);
        float xc = c + 1.0f;
        int idx = min(max((int)floorf(xc * inv_hg), 0), K - 2);
        float s = xc - (float)idx * hg;
        float4 cf = g_gc[idx];
        float gv = cf.x + s * (cf.y + s * (cf.z + s * cf.w));
        acc += (s1 != d2) ? u1.w * u2.w * gv : 0.0f;
    }
#pragma unroll
    for (int o = 16; o; o >>= 1) acc += __shfl_down_sync(0xffffffffu, acc, o);
    if (lane == 0) out[e2] = acc;
}

// ===========================================================================
template <int K>
static void launch_ct(const float* r, const float* fy, const float* gy,
                      const int* src, const int* dst, float* out, int E) {
    smeam_edge_kernel<K><<<(E + 255) / 256, 256>>>(r, fy, src, dst, E);
    // Single-wave persistent grid: ~4 resident blocks/SM expected at ~60
    // regs x 148 SMs = 592 blocks of 256 threads.
    const int t = 256;
    long need_warps = (long)(E >> 3) + 8;       // groups + tail
    int need_blocks = (int)((need_warps * 32 + t - 1) / t);
    int blocks = 592;
    if (need_blocks < blocks) blocks = need_blocks;
    if (blocks < 1) blocks = 1;
    smeam_main_gather<K><<<blocks, t>>>(src, dst, gy, out, E);
}

extern "C" void kernel_launch(void* const* d_in, const int* in_sizes, int n_in,
                              void* d_out, int out_size) {
    const float* r   = (const float*)d_in[0];
    const float* fy  = (const float*)d_in[1];
    const float* gy  = (const float*)d_in[2];
    const int*   src = (const int*)d_in[3];
    const int*   dst = (const int*)d_in[4];
    float*       out = (float*)d_out;

    int E = in_sizes[3];
    int K = in_sizes[1];

    switch (K) {
        case 3: launch_ct<3>(r, fy, gy, src, dst, out, E); break;
        case 4: launch_ct<4>(r, fy, gy, src, dst, out, E); break;
        case 5: launch_ct<5>(r, fy, gy, src, dst, out, E); break;
        case 6: launch_ct<6>(r, fy, gy, src, dst, out, E); break;
        case 7: launch_ct<7>(r, fy, gy, src, dst, out, E); break;
        case 8: launch_ct<8>(r, fy, gy, src, dst, out, E); break;
        case 9: launch_ct<9>(r, fy, gy, src, dst, out, E); break;
        default: {
            smeam_build_kernel_rt<<<1, 1>>>(fy, gy, dst, E, K);
            int t = 256;
            smeam_edge_kernel_rt<<<(E + t - 1) / t, t>>>(r, E, K);
            long total = (long)E * 32;
            unsigned blocks = (unsigned)((total + t - 1) / t);
            smeam_main_kernel_rt<<<blocks, t>>>(src, dst, out, E, K);
            break;
        }
    }
}